// round 1
// baseline (speedup 1.0000x reference)
#include <cuda_runtime.h>
#include <math.h>

#define B_ROWS 4096
#define NROWS  8192          // 2B
#define DDIM   1024
#define INV_T  10.0f         // 1 / temperature

// ---------------- device scratch (static allocation; no cudaMalloc) ----------
__device__ float g_reps[NROWS * DDIM];   // normalized rows, fp32 (32 MB)
__device__ float g_rowsum[NROWS];        // sum_{j != i} exp(sim_ij)
__device__ float g_pos[NROWS];           // sim[i, i +- B]

// ---------------- kernel 1: row L2-normalize + zero rowsum -------------------
__global__ void normalize_kernel(const float* __restrict__ z1,
                                 const float* __restrict__ z2) {
    int row = blockIdx.x;                       // 0..8191
    const float* src = (row < B_ROWS) ? (z1 + (size_t)row * DDIM)
                                      : (z2 + (size_t)(row - B_ROWS) * DDIM);
    int t = threadIdx.x;                        // 256 threads, 4 floats each
    float4 v = reinterpret_cast<const float4*>(src)[t];
    float s = v.x * v.x + v.y * v.y + v.z * v.z + v.w * v.w;

    __shared__ float sh[8];
    #pragma unroll
    for (int o = 16; o > 0; o >>= 1) s += __shfl_xor_sync(0xffffffffu, s, o);
    if ((t & 31) == 0) sh[t >> 5] = s;
    __syncthreads();
    if (t < 8) {
        float x = sh[t];
        #pragma unroll
        for (int o = 4; o > 0; o >>= 1) x += __shfl_xor_sync(0x000000ffu, x, o);
        if (t == 0) sh[0] = x;
    }
    __syncthreads();
    float norm = sqrtf(sh[0]);
    float inv  = 1.0f / fmaxf(norm, 1e-12f);

    float4 o4;
    o4.x = v.x * inv; o4.y = v.y * inv; o4.z = v.z * inv; o4.w = v.w * inv;
    reinterpret_cast<float4*>(g_reps + (size_t)row * DDIM)[t] = o4;
    if (t == 0) g_rowsum[row] = 0.0f;
}

// ---------------- kernel 2: fused GEMM + exp + row-sum -----------------------
// Tile: BM=BN=128, BK=16. 256 threads, each computes an 8x8 micro-tile
// arranged as 2x2 groups of 4x4 (rows ty*4 and 64+ty*4; cols tx*4 and 64+tx*4).
#define BM 128
#define BN 128
#define BK 16
#define SPAD 4

__global__ void __launch_bounds__(256) simgemm_kernel() {
    __shared__ float As[BK][BM + SPAD];
    __shared__ float Bs[BK][BN + SPAD];

    int tid = threadIdx.x;
    int tx = tid & 15;         // 0..15
    int ty = tid >> 4;         // 0..15
    int I0 = blockIdx.y * BM;
    int J0 = blockIdx.x * BN;

    const float* Abase = g_reps + (size_t)I0 * DDIM;
    const float* Bbase = g_reps + (size_t)J0 * DDIM;

    int lrow = tid >> 2;           // 0..63
    int lcol = (tid & 3) << 2;     // 0,4,8,12

    float acc[8][8];
    #pragma unroll
    for (int a = 0; a < 8; a++)
        #pragma unroll
        for (int b = 0; b < 8; b++) acc[a][b] = 0.0f;

    for (int k0 = 0; k0 < DDIM; k0 += BK) {
        #pragma unroll
        for (int half = 0; half < 2; half++) {
            int r = lrow + half * 64;
            float4 a = *reinterpret_cast<const float4*>(Abase + (size_t)r * DDIM + k0 + lcol);
            As[lcol + 0][r] = a.x; As[lcol + 1][r] = a.y;
            As[lcol + 2][r] = a.z; As[lcol + 3][r] = a.w;
            float4 b = *reinterpret_cast<const float4*>(Bbase + (size_t)r * DDIM + k0 + lcol);
            Bs[lcol + 0][r] = b.x; Bs[lcol + 1][r] = b.y;
            Bs[lcol + 2][r] = b.z; Bs[lcol + 3][r] = b.w;
        }
        __syncthreads();

        #pragma unroll
        for (int k = 0; k < BK; k++) {
            float am[8], bn[8];
            float4 a0 = *reinterpret_cast<const float4*>(&As[k][ty * 4]);
            float4 a1 = *reinterpret_cast<const float4*>(&As[k][64 + ty * 4]);
            float4 b0 = *reinterpret_cast<const float4*>(&Bs[k][tx * 4]);
            float4 b1 = *reinterpret_cast<const float4*>(&Bs[k][64 + tx * 4]);
            am[0]=a0.x; am[1]=a0.y; am[2]=a0.z; am[3]=a0.w;
            am[4]=a1.x; am[5]=a1.y; am[6]=a1.z; am[7]=a1.w;
            bn[0]=b0.x; bn[1]=b0.y; bn[2]=b0.z; bn[3]=b0.w;
            bn[4]=b1.x; bn[5]=b1.y; bn[6]=b1.z; bn[7]=b1.w;
            #pragma unroll
            for (int a = 0; a < 8; a++)
                #pragma unroll
                for (int b = 0; b < 8; b++)
                    acc[a][b] += am[a] * bn[b];
        }
        __syncthreads();
    }

    // epilogue: sim = acc * INV_T; capture positives; rowsum of exp (skip j==i)
    #pragma unroll
    for (int a = 0; a < 8; a++) {
        int il = (a < 4) ? (ty * 4 + a) : (64 + ty * 4 + (a - 4));
        int i  = I0 + il;
        float rs = 0.0f;
        #pragma unroll
        for (int b = 0; b < 8; b++) {
            int jl = (b < 4) ? (tx * 4 + b) : (64 + tx * 4 + (b - 4));
            int j  = J0 + jl;
            float s = acc[a][b] * INV_T;
            if (j == i + B_ROWS || i == j + B_ROWS) g_pos[i] = s;
            rs += (j == i) ? 0.0f : __expf(s);
        }
        // reduce over the 16 tx lanes (each half-warp is one ty group)
        #pragma unroll
        for (int o = 1; o < 16; o <<= 1) rs += __shfl_xor_sync(0xffffffffu, rs, o);
        if (tx == 0) atomicAdd(&g_rowsum[i], rs);
    }
}

// ---------------- kernel 3: final loss ---------------------------------------
__global__ void loss_kernel(float* __restrict__ out) {
    int t = threadIdx.x;  // 256
    float s = 0.0f;
    for (int i = t; i < NROWS; i += 256) {
        float p  = g_pos[i];
        float l  = logf(expf(p) + g_rowsum[i]);   // lse including pos twice (matches ref)
        s += l - p;
    }
    __shared__ float sh[8];
    #pragma unroll
    for (int o = 16; o > 0; o >>= 1) s += __shfl_xor_sync(0xffffffffu, s, o);
    if ((t & 31) == 0) sh[t >> 5] = s;
    __syncthreads();
    if (t < 8) {
        float x = sh[t];
        #pragma unroll
        for (int o = 4; o > 0; o >>= 1) x += __shfl_xor_sync(0x000000ffu, x, o);
        if (t == 0) out[0] = x / (float)NROWS;
    }
}

// ---------------- launcher ----------------------------------------------------
extern "C" void kernel_launch(void* const* d_in, const int* in_sizes, int n_in,
                              void* d_out, int out_size) {
    const float* z1 = (const float*)d_in[0];
    const float* z2 = (const float*)d_in[1];
    float* out = (float*)d_out;

    normalize_kernel<<<NROWS, 256>>>(z1, z2);
    dim3 grid(NROWS / BN, NROWS / BM);
    simgemm_kernel<<<grid, 256>>>();
    loss_kernel<<<1, 256>>>(out);
}

// round 3
// speedup vs baseline: 10.3371x; 10.3371x over previous
#include <cuda_runtime.h>
#include <cuda_bf16.h>
#include <math.h>
#include <stdint.h>

#define B_ROWS 4096
#define NROWS  8192          // 2B
#define DDIM   1024
#define INV_T  10.0f
#define NTILE  64            // NROWS / 128

#define BK     32
#define BKP    40            // padded bf16 cols (80B row stride, conflict-free for ldmatrix)
#define STAGES (DDIM / BK)   // 32

// ---------------- device scratch ---------------------------------------------
__device__ __align__(128) __nv_bfloat16 g_reps[NROWS * DDIM];  // normalized rows, bf16
__device__ float g_rowsum[NROWS];
__device__ float g_pos[NROWS];

// ---------------- helpers ------------------------------------------------------
__device__ __forceinline__ uint32_t smem_u32(const void* p) {
    uint32_t a;
    asm("{ .reg .u64 t; cvta.to.shared.u64 t, %1; cvt.u32.u64 %0, t; }" : "=r"(a) : "l"(p));
    return a;
}
__device__ __forceinline__ void cp16(uint32_t saddr, const void* gptr) {
    asm volatile("cp.async.cg.shared.global [%0], [%1], 16;" :: "r"(saddr), "l"(gptr) : "memory");
}
__device__ __forceinline__ void ldm_x4(uint32_t addr, uint32_t& r0, uint32_t& r1,
                                       uint32_t& r2, uint32_t& r3) {
    asm volatile("ldmatrix.sync.aligned.m8n8.x4.shared.b16 {%0,%1,%2,%3}, [%4];"
                 : "=r"(r0), "=r"(r1), "=r"(r2), "=r"(r3) : "r"(addr));
}
__device__ __forceinline__ void mma16816(float& d0, float& d1, float& d2, float& d3,
                                         uint32_t a0, uint32_t a1, uint32_t a2, uint32_t a3,
                                         uint32_t b0, uint32_t b1) {
    asm volatile(
        "mma.sync.aligned.m16n8k16.row.col.f32.bf16.bf16.f32 "
        "{%0,%1,%2,%3}, {%4,%5,%6,%7}, {%8,%9}, {%0,%1,%2,%3};"
        : "+f"(d0), "+f"(d1), "+f"(d2), "+f"(d3)
        : "r"(a0), "r"(a1), "r"(a2), "r"(a3), "r"(b0), "r"(b1));
}

// ---------------- kernel 1: row L2-normalize -> bf16, zero rowsum -------------
__global__ void normalize_kernel(const float* __restrict__ z1,
                                 const float* __restrict__ z2) {
    int row = blockIdx.x;
    const float* src = (row < B_ROWS) ? (z1 + (size_t)row * DDIM)
                                      : (z2 + (size_t)(row - B_ROWS) * DDIM);
    int t = threadIdx.x;                        // 256 threads * 4 floats
    float4 v = reinterpret_cast<const float4*>(src)[t];
    float s = v.x * v.x + v.y * v.y + v.z * v.z + v.w * v.w;

    __shared__ float sh[8];
    #pragma unroll
    for (int o = 16; o > 0; o >>= 1) s += __shfl_xor_sync(0xffffffffu, s, o);
    if ((t & 31) == 0) sh[t >> 5] = s;
    __syncthreads();
    if (t < 8) {
        float x = sh[t];
        #pragma unroll
        for (int o = 4; o > 0; o >>= 1) x += __shfl_xor_sync(0x000000ffu, x, o);
        if (t == 0) sh[0] = x;
    }
    __syncthreads();
    float inv = 1.0f / fmaxf(sqrtf(sh[0]), 1e-12f);

    __nv_bfloat162* dst = reinterpret_cast<__nv_bfloat162*>(g_reps + (size_t)row * DDIM);
    dst[2 * t + 0] = __floats2bfloat162_rn(v.x * inv, v.y * inv);
    dst[2 * t + 1] = __floats2bfloat162_rn(v.z * inv, v.w * inv);
    if (t == 0) g_rowsum[row] = 0.0f;
}

// ---------------- kernel 2: HMMA GEMM (upper triangle) + fused epilogue -------
// 256 threads = 8 warps in 2x4 grid; warp tile 64x32; thread frags via mma.m16n8k16.
__global__ void __launch_bounds__(256, 2) simgemm_hmma() {
    __shared__ __nv_bfloat16 sA[2][128 * BKP];
    __shared__ __nv_bfloat16 sB[2][128 * BKP];

    int tid = threadIdx.x;
    int wid = tid >> 5;
    int lid = tid & 31;
    int wr = wid >> 2;          // 0..1  (row group of 64)
    int wc = wid & 3;           // 0..3  (col group of 32)

    // --- linear block id -> upper-triangle tile (I, J), J >= I ---
    int t = blockIdx.x;
    int I = (int)((129.0f - sqrtf(16641.0f - 8.0f * (float)t)) * 0.5f);
    if (I < 0) I = 0;
    if (I > NTILE - 1) I = NTILE - 1;
    while (I > 0 && I * (129 - I) / 2 > t) --I;
    while (I < NTILE - 1 && (I + 1) * (128 - I) / 2 <= t) ++I;
    int J = I + (t - I * (129 - I) / 2);
    int I0 = I * 128, J0 = J * 128;
    bool diag = (I == J);
    bool posTile = (J == I + 32);    // J0 == I0 + B_ROWS

    const __nv_bfloat16* gA = g_reps + (size_t)I0 * DDIM;
    const __nv_bfloat16* gB = g_reps + (size_t)J0 * DDIM;

    float acc[4][4][4];
    #pragma unroll
    for (int a = 0; a < 4; a++)
        #pragma unroll
        for (int b = 0; b < 4; b++)
            #pragma unroll
            for (int c = 0; c < 4; c++) acc[a][b][c] = 0.0f;

    // chunk mapping for cp.async: 512 16B-chunks per operand per stage
    int c0 = tid, c1 = tid + 256;
    int r0c = c0 >> 2, k0c = (c0 & 3) << 3;    // row, bf16-col
    int r1c = c1 >> 2, k1c = (c1 & 3) << 3;

    uint32_t sA0[2], sA1[2], sB0[2], sB1[2];
    #pragma unroll
    for (int b = 0; b < 2; b++) {
        sA0[b] = smem_u32(&sA[b][r0c * BKP + k0c]);
        sA1[b] = smem_u32(&sA[b][r1c * BKP + k1c]);
        sB0[b] = smem_u32(&sB[b][r0c * BKP + k0c]);
        sB1[b] = smem_u32(&sB[b][r1c * BKP + k1c]);
    }

    // prologue: stage 0
    {
        cp16(sA0[0], gA + (size_t)r0c * DDIM + k0c);
        cp16(sA1[0], gA + (size_t)r1c * DDIM + k1c);
        cp16(sB0[0], gB + (size_t)r0c * DDIM + k0c);
        cp16(sB1[0], gB + (size_t)r1c * DDIM + k1c);
        asm volatile("cp.async.commit_group;" ::: "memory");
    }

    // frag base offsets (within a buffer)
    int aRow = wr * 64 + (lid & 15);
    int aColSel = (lid >> 4) << 3;
    int bRow = wc * 32 + (lid & 7) + ((lid >> 4) << 3);  // n within warp tile (pair base added later)
    int bColSel = ((lid >> 3) & 1) << 3;

    for (int s = 0; s < STAGES; ++s) {
        int buf = s & 1;
        if (s + 1 < STAGES) {
            int k0 = (s + 1) * BK;
            int nb = (s + 1) & 1;
            cp16(sA0[nb], gA + (size_t)r0c * DDIM + k0 + k0c);
            cp16(sA1[nb], gA + (size_t)r1c * DDIM + k0 + k1c);
            cp16(sB0[nb], gB + (size_t)r0c * DDIM + k0 + k0c);
            cp16(sB1[nb], gB + (size_t)r1c * DDIM + k0 + k1c);
            asm volatile("cp.async.commit_group;" ::: "memory");
            asm volatile("cp.async.wait_group 1;" ::: "memory");
        } else {
            asm volatile("cp.async.wait_group 0;" ::: "memory");
        }
        __syncthreads();

        #pragma unroll
        for (int ks = 0; ks < BK / 16; ++ks) {
            int kk = ks * 16;
            uint32_t a[4][4], b[2][4];
            #pragma unroll
            for (int mt = 0; mt < 4; ++mt) {
                uint32_t addr = smem_u32(&sA[buf][(aRow + mt * 16) * BKP + kk + aColSel]);
                ldm_x4(addr, a[mt][0], a[mt][1], a[mt][2], a[mt][3]);
            }
            #pragma unroll
            for (int np = 0; np < 2; ++np) {
                uint32_t addr = smem_u32(&sB[buf][(bRow + np * 16) * BKP + kk + bColSel]);
                ldm_x4(addr, b[np][0], b[np][1], b[np][2], b[np][3]);
            }
            #pragma unroll
            for (int mt = 0; mt < 4; ++mt)
                #pragma unroll
                for (int nt = 0; nt < 4; ++nt) {
                    uint32_t bb0 = (nt & 1) ? b[nt >> 1][2] : b[nt >> 1][0];
                    uint32_t bb1 = (nt & 1) ? b[nt >> 1][3] : b[nt >> 1][1];
                    mma16816(acc[mt][nt][0], acc[mt][nt][1], acc[mt][nt][2], acc[mt][nt][3],
                             a[mt][0], a[mt][1], a[mt][2], a[mt][3], bb0, bb1);
                }
        }
        __syncthreads();
    }

    // --- epilogue: fused *INV_T, exp, positive capture, row+col sums ---------
    int rBase = I0 + wr * 64;
    int cBase = J0 + wc * 32;
    float rowacc[4][2];
    float colacc[4][2];
    #pragma unroll
    for (int x = 0; x < 4; ++x) { rowacc[x][0] = rowacc[x][1] = 0.0f;
                                  colacc[x][0] = colacc[x][1] = 0.0f; }

    #pragma unroll
    for (int mt = 0; mt < 4; ++mt) {
        int i0 = rBase + mt * 16 + (lid >> 2);
        int i1 = i0 + 8;
        #pragma unroll
        for (int nt = 0; nt < 4; ++nt) {
            int j0 = cBase + nt * 8 + (lid & 3) * 2;
            int j1 = j0 + 1;
            float s00 = acc[mt][nt][0] * INV_T;
            float s01 = acc[mt][nt][1] * INV_T;
            float s10 = acc[mt][nt][2] * INV_T;
            float s11 = acc[mt][nt][3] * INV_T;
            if (posTile) {
                if (j0 == i0 + B_ROWS) { g_pos[i0] = s00; g_pos[j0] = s00; }
                if (j1 == i0 + B_ROWS) { g_pos[i0] = s01; g_pos[j1] = s01; }
                if (j0 == i1 + B_ROWS) { g_pos[i1] = s10; g_pos[j0] = s10; }
                if (j1 == i1 + B_ROWS) { g_pos[i1] = s11; g_pos[j1] = s11; }
            }
            float e00 = (diag && j0 == i0) ? 0.0f : __expf(s00);
            float e01 = (diag && j1 == i0) ? 0.0f : __expf(s01);
            float e10 = (diag && j0 == i1) ? 0.0f : __expf(s10);
            float e11 = (diag && j1 == i1) ? 0.0f : __expf(s11);
            rowacc[mt][0] += e00 + e01;
            rowacc[mt][1] += e10 + e11;
            colacc[nt][0] += e00 + e10;
            colacc[nt][1] += e01 + e11;
        }
    }

    // row sums: reduce over the 4 lanes sharing a row (lane bits 0-1)
    #pragma unroll
    for (int mt = 0; mt < 4; ++mt) {
        float r0 = rowacc[mt][0], r1 = rowacc[mt][1];
        #pragma unroll
        for (int o = 1; o < 4; o <<= 1) {
            r0 += __shfl_xor_sync(0xffffffffu, r0, o);
            r1 += __shfl_xor_sync(0xffffffffu, r1, o);
        }
        if ((lid & 3) == 0) {
            int i0 = rBase + mt * 16 + (lid >> 2);
            atomicAdd(&g_rowsum[i0], r0);
            atomicAdd(&g_rowsum[i0 + 8], r1);
        }
    }

    // col sums (off-diagonal tiles only): reduce over lane bits 2-4
    if (!diag) {
        #pragma unroll
        for (int nt = 0; nt < 4; ++nt) {
            float cA = colacc[nt][0], cB = colacc[nt][1];
            #pragma unroll
            for (int o = 4; o < 32; o <<= 1) {
                cA += __shfl_xor_sync(0xffffffffu, cA, o);
                cB += __shfl_xor_sync(0xffffffffu, cB, o);
            }
            if (lid < 4) {
                int j0 = cBase + nt * 8 + lid * 2;
                if ((lid & 3) == (j0 & 7) / 2) { /* lane owns its col pair */ }
                atomicAdd(&g_rowsum[j0], cA);
                atomicAdd(&g_rowsum[j0 + 1], cB);
            }
        }
    }
}

// ---------------- kernel 3: final loss -----------------------------------------
__global__ void loss_kernel(float* __restrict__ out) {
    int t = threadIdx.x;
    float s = 0.0f;
    for (int i = t; i < NROWS; i += 256) {
        float p = g_pos[i];
        s += logf(expf(p) + g_rowsum[i]) - p;
    }
    __shared__ float sh[8];
    #pragma unroll
    for (int o = 16; o > 0; o >>= 1) s += __shfl_xor_sync(0xffffffffu, s, o);
    if ((t & 31) == 0) sh[t >> 5] = s;
    __syncthreads();
    if (t < 8) {
        float x = sh[t];
        #pragma unroll
        for (int o = 4; o > 0; o >>= 1) x += __shfl_xor_sync(0x000000ffu, x, o);
        if (t == 0) out[0] = x / (float)NROWS;
    }
}

// ---------------- launcher ------------------------------------------------------
extern "C" void kernel_launch(void* const* d_in, const int* in_sizes, int n_in,
                              void* d_out, int out_size) {
    const float* z1 = (const float*)d_in[0];
    const float* z2 = (const float*)d_in[1];
    float* out = (float*)d_out;

    normalize_kernel<<<NROWS, 256>>>(z1, z2);
    simgemm_hmma<<<NTILE * (NTILE + 1) / 2, 256>>>();   // 2080 upper-triangle tiles
    loss_kernel<<<1, 256>>>(out);
}

// round 4
// speedup vs baseline: 11.2346x; 1.0868x over previous
#include <cuda_runtime.h>
#include <cuda_bf16.h>
#include <math.h>
#include <stdint.h>

#define B_ROWS 4096
#define NROWS  8192          // 2B
#define DDIM   1024
#define INV_T  10.0f
#define NTILE  64            // NROWS / 128

#define BK     32
#define BKP    40            // padded bf16 cols (80B row stride, conflict-free ldmatrix)
#define STAGES (DDIM / BK)   // 32
#define PIPE   4             // cp.async pipeline depth
#define BUFE   (128 * BKP)   // bf16 elems per operand per stage buffer

// ---------------- device scratch ---------------------------------------------
__device__ __align__(128) __nv_bfloat16 g_reps[NROWS * DDIM];  // normalized rows
__device__ float g_rowsum[NROWS];
__device__ float g_pos[NROWS];

// ---------------- helpers ------------------------------------------------------
__device__ __forceinline__ uint32_t smem_u32(const void* p) {
    uint32_t a;
    asm("{ .reg .u64 t; cvta.to.shared.u64 t, %1; cvt.u32.u64 %0, t; }" : "=r"(a) : "l"(p));
    return a;
}
__device__ __forceinline__ void cp16(uint32_t saddr, const void* gptr) {
    asm volatile("cp.async.cg.shared.global [%0], [%1], 16;" :: "r"(saddr), "l"(gptr) : "memory");
}
__device__ __forceinline__ void ldm_x4(uint32_t addr, uint32_t& r0, uint32_t& r1,
                                       uint32_t& r2, uint32_t& r3) {
    asm volatile("ldmatrix.sync.aligned.m8n8.x4.shared.b16 {%0,%1,%2,%3}, [%4];"
                 : "=r"(r0), "=r"(r1), "=r"(r2), "=r"(r3) : "r"(addr));
}
__device__ __forceinline__ void mma16816(float& d0, float& d1, float& d2, float& d3,
                                         uint32_t a0, uint32_t a1, uint32_t a2, uint32_t a3,
                                         uint32_t b0, uint32_t b1) {
    asm volatile(
        "mma.sync.aligned.m16n8k16.row.col.f32.bf16.bf16.f32 "
        "{%0,%1,%2,%3}, {%4,%5,%6,%7}, {%8,%9}, {%0,%1,%2,%3};"
        : "+f"(d0), "+f"(d1), "+f"(d2), "+f"(d3)
        : "r"(a0), "r"(a1), "r"(a2), "r"(a3), "r"(b0), "r"(b1));
}

// ---------------- kernel 1: row L2-normalize -> bf16, zero rowsum -------------
__global__ void normalize_kernel(const float* __restrict__ z1,
                                 const float* __restrict__ z2) {
    int row = blockIdx.x;
    const float* src = (row < B_ROWS) ? (z1 + (size_t)row * DDIM)
                                      : (z2 + (size_t)(row - B_ROWS) * DDIM);
    int t = threadIdx.x;                        // 256 threads * 4 floats
    float4 v = reinterpret_cast<const float4*>(src)[t];
    float s = v.x * v.x + v.y * v.y + v.z * v.z + v.w * v.w;

    __shared__ float sh[8];
    #pragma unroll
    for (int o = 16; o > 0; o >>= 1) s += __shfl_xor_sync(0xffffffffu, s, o);
    if ((t & 31) == 0) sh[t >> 5] = s;
    __syncthreads();
    if (t < 8) {
        float x = sh[t];
        #pragma unroll
        for (int o = 4; o > 0; o >>= 1) x += __shfl_xor_sync(0x000000ffu, x, o);
        if (t == 0) sh[0] = x;
    }
    __syncthreads();
    float inv = 1.0f / fmaxf(sqrtf(sh[0]), 1e-12f);

    __nv_bfloat162* dst = reinterpret_cast<__nv_bfloat162*>(g_reps + (size_t)row * DDIM);
    dst[2 * t + 0] = __floats2bfloat162_rn(v.x * inv, v.y * inv);
    dst[2 * t + 1] = __floats2bfloat162_rn(v.z * inv, v.w * inv);
    if (t == 0) g_rowsum[row] = 0.0f;
}

// ---------------- kernel 2: HMMA GEMM (upper triangle) + fused epilogue -------
// 256 threads = 8 warps (2x4); warp tile 64x32; 4-deep cp.async pipeline, BK=32.
extern __shared__ __nv_bfloat16 dsm[];   // [PIPE * BUFE] A then [PIPE * BUFE] B

__global__ void __launch_bounds__(256, 2) simgemm_hmma() {
    int tid = threadIdx.x;
    int wid = tid >> 5;
    int lid = tid & 31;
    int wr = wid >> 2;          // 0..1
    int wc = wid & 3;           // 0..3

    // --- linear block id -> upper-triangle tile (I, J), J >= I ---
    int t = blockIdx.x;
    int I = (int)((129.0f - sqrtf(16641.0f - 8.0f * (float)t)) * 0.5f);
    if (I < 0) I = 0;
    if (I > NTILE - 1) I = NTILE - 1;
    while (I > 0 && I * (129 - I) / 2 > t) --I;
    while (I < NTILE - 1 && (I + 1) * (128 - I) / 2 <= t) ++I;
    int J = I + (t - I * (129 - I) / 2);
    int I0 = I * 128, J0 = J * 128;
    bool diag = (I == J);
    bool posTile = (J == I + 32);    // J0 == I0 + B_ROWS

    const __nv_bfloat16* gA = g_reps + (size_t)I0 * DDIM;
    const __nv_bfloat16* gB = g_reps + (size_t)J0 * DDIM;

    float acc[4][4][4];
    #pragma unroll
    for (int a = 0; a < 4; a++)
        #pragma unroll
        for (int b = 0; b < 4; b++)
            #pragma unroll
            for (int c = 0; c < 4; c++) acc[a][b][c] = 0.0f;

    // cp.async chunk mapping: 512 16B-chunks per operand per stage
    int c0 = tid, c1 = tid + 256;
    int r0c = c0 >> 2, k0c = (c0 & 3) << 3;    // row, bf16-col within slab
    int r1c = c1 >> 2, k1c = (c1 & 3) << 3;

    uint32_t aBase[PIPE], a1Base[PIPE], bBase[PIPE], b1Base[PIPE];
    #pragma unroll
    for (int b = 0; b < PIPE; b++) {
        aBase[b]  = smem_u32(&dsm[(size_t)b * BUFE + r0c * BKP + k0c]);
        a1Base[b] = smem_u32(&dsm[(size_t)b * BUFE + r1c * BKP + k1c]);
        bBase[b]  = smem_u32(&dsm[(size_t)(PIPE + b) * BUFE + r0c * BKP + k0c]);
        b1Base[b] = smem_u32(&dsm[(size_t)(PIPE + b) * BUFE + r1c * BKP + k1c]);
    }

    // prologue: stages 0..PIPE-2 (3 groups in flight)
    #pragma unroll
    for (int s = 0; s < PIPE - 1; ++s) {
        int k0 = s * BK;
        cp16(aBase[s],  gA + (size_t)r0c * DDIM + k0 + k0c);
        cp16(a1Base[s], gA + (size_t)r1c * DDIM + k0 + k1c);
        cp16(bBase[s],  gB + (size_t)r0c * DDIM + k0 + k0c);
        cp16(b1Base[s], gB + (size_t)r1c * DDIM + k0 + k1c);
        asm volatile("cp.async.commit_group;" ::: "memory");
    }

    // frag offsets
    int aRow = wr * 64 + (lid & 15);
    int aColSel = (lid >> 4) << 3;
    int bRow = wc * 32 + (lid & 7) + ((lid >> 4) << 3);
    int bColSel = ((lid >> 3) & 1) << 3;
    const __nv_bfloat16* sAe = dsm;
    const __nv_bfloat16* sBe = dsm + (size_t)PIPE * BUFE;

    for (int s = 0; s < STAGES; ++s) {
        int buf = s & (PIPE - 1);
        asm volatile("cp.async.wait_group %0;" :: "n"(PIPE - 2) : "memory");
        __syncthreads();

        // issue load of stage s+PIPE-1 into the buffer last read at stage s-1
        {
            int sn = s + PIPE - 1;
            if (sn < STAGES) {
                int nb = sn & (PIPE - 1);
                int k0 = sn * BK;
                cp16(aBase[nb],  gA + (size_t)r0c * DDIM + k0 + k0c);
                cp16(a1Base[nb], gA + (size_t)r1c * DDIM + k0 + k1c);
                cp16(bBase[nb],  gB + (size_t)r0c * DDIM + k0 + k0c);
                cp16(b1Base[nb], gB + (size_t)r1c * DDIM + k0 + k1c);
            }
            asm volatile("cp.async.commit_group;" ::: "memory");  // maybe-empty: keeps count uniform
        }

        #pragma unroll
        for (int ks = 0; ks < BK / 16; ++ks) {
            int kk = ks * 16;
            uint32_t a[4][4], b[2][4];
            #pragma unroll
            for (int mt = 0; mt < 4; ++mt) {
                uint32_t addr = smem_u32(&sAe[(size_t)buf * BUFE + (aRow + mt * 16) * BKP + kk + aColSel]);
                ldm_x4(addr, a[mt][0], a[mt][1], a[mt][2], a[mt][3]);
            }
            #pragma unroll
            for (int np = 0; np < 2; ++np) {
                uint32_t addr = smem_u32(&sBe[(size_t)buf * BUFE + (bRow + np * 16) * BKP + kk + bColSel]);
                ldm_x4(addr, b[np][0], b[np][1], b[np][2], b[np][3]);
            }
            #pragma unroll
            for (int mt = 0; mt < 4; ++mt)
                #pragma unroll
                for (int nt = 0; nt < 4; ++nt) {
                    uint32_t bb0 = (nt & 1) ? b[nt >> 1][2] : b[nt >> 1][0];
                    uint32_t bb1 = (nt & 1) ? b[nt >> 1][3] : b[nt >> 1][1];
                    mma16816(acc[mt][nt][0], acc[mt][nt][1], acc[mt][nt][2], acc[mt][nt][3],
                             a[mt][0], a[mt][1], a[mt][2], a[mt][3], bb0, bb1);
                }
        }
    }

    // --- epilogue: fused *INV_T, exp, positive capture, row+col sums ---------
    int rBase = I0 + wr * 64;
    int cBase = J0 + wc * 32;
    float rowacc[4][2];
    float colacc[4][2];
    #pragma unroll
    for (int x = 0; x < 4; ++x) { rowacc[x][0] = rowacc[x][1] = 0.0f;
                                  colacc[x][0] = colacc[x][1] = 0.0f; }

    #pragma unroll
    for (int mt = 0; mt < 4; ++mt) {
        int i0 = rBase + mt * 16 + (lid >> 2);
        int i1 = i0 + 8;
        #pragma unroll
        for (int nt = 0; nt < 4; ++nt) {
            int j0 = cBase + nt * 8 + (lid & 3) * 2;
            int j1 = j0 + 1;
            float s00 = acc[mt][nt][0] * INV_T;
            float s01 = acc[mt][nt][1] * INV_T;
            float s10 = acc[mt][nt][2] * INV_T;
            float s11 = acc[mt][nt][3] * INV_T;
            if (posTile) {
                if (j0 == i0 + B_ROWS) { g_pos[i0] = s00; g_pos[j0] = s00; }
                if (j1 == i0 + B_ROWS) { g_pos[i0] = s01; g_pos[j1] = s01; }
                if (j0 == i1 + B_ROWS) { g_pos[i1] = s10; g_pos[j0] = s10; }
                if (j1 == i1 + B_ROWS) { g_pos[i1] = s11; g_pos[j1] = s11; }
            }
            float e00 = (diag && j0 == i0) ? 0.0f : __expf(s00);
            float e01 = (diag && j1 == i0) ? 0.0f : __expf(s01);
            float e10 = (diag && j0 == i1) ? 0.0f : __expf(s10);
            float e11 = (diag && j1 == i1) ? 0.0f : __expf(s11);
            rowacc[mt][0] += e00 + e01;
            rowacc[mt][1] += e10 + e11;
            colacc[nt][0] += e00 + e10;
            colacc[nt][1] += e01 + e11;
        }
    }

    #pragma unroll
    for (int mt = 0; mt < 4; ++mt) {
        float r0 = rowacc[mt][0], r1 = rowacc[mt][1];
        #pragma unroll
        for (int o = 1; o < 4; o <<= 1) {
            r0 += __shfl_xor_sync(0xffffffffu, r0, o);
            r1 += __shfl_xor_sync(0xffffffffu, r1, o);
        }
        if ((lid & 3) == 0) {
            int i0 = rBase + mt * 16 + (lid >> 2);
            atomicAdd(&g_rowsum[i0], r0);
            atomicAdd(&g_rowsum[i0 + 8], r1);
        }
    }

    if (!diag) {
        #pragma unroll
        for (int nt = 0; nt < 4; ++nt) {
            float cA = colacc[nt][0], cB = colacc[nt][1];
            #pragma unroll
            for (int o = 4; o < 32; o <<= 1) {
                cA += __shfl_xor_sync(0xffffffffu, cA, o);
                cB += __shfl_xor_sync(0xffffffffu, cB, o);
            }
            if (lid < 4) {
                int j0 = cBase + nt * 8 + lid * 2;
                atomicAdd(&g_rowsum[j0], cA);
                atomicAdd(&g_rowsum[j0 + 1], cB);
            }
        }
    }
}

// ---------------- kernel 3: final loss -----------------------------------------
__global__ void loss_kernel(float* __restrict__ out) {
    int t = threadIdx.x;
    float s = 0.0f;
    for (int i = t; i < NROWS; i += 512) {
        float p = g_pos[i];
        s += logf(expf(p) + g_rowsum[i]) - p;
    }
    __shared__ float sh[16];
    #pragma unroll
    for (int o = 16; o > 0; o >>= 1) s += __shfl_xor_sync(0xffffffffu, s, o);
    if ((t & 31) == 0) sh[t >> 5] = s;
    __syncthreads();
    if (t < 16) {
        float x = sh[t];
        #pragma unroll
        for (int o = 8; o > 0; o >>= 1) x += __shfl_xor_sync(0x0000ffffu, x, o);
        if (t == 0) out[0] = x / (float)NROWS;
    }
}

// ---------------- launcher ------------------------------------------------------
extern "C" void kernel_launch(void* const* d_in, const int* in_sizes, int n_in,
                              void* d_out, int out_size) {
    const float* z1 = (const float*)d_in[0];
    const float* z2 = (const float*)d_in[1];
    float* out = (float*)d_out;

    const int smemBytes = 2 * PIPE * BUFE * (int)sizeof(__nv_bfloat16);   // 81920
    cudaFuncSetAttribute(simgemm_hmma, cudaFuncAttributeMaxDynamicSharedMemorySize, smemBytes);

    normalize_kernel<<<NROWS, 256>>>(z1, z2);
    simgemm_hmma<<<NTILE * (NTILE + 1) / 2, 256, smemBytes>>>();
    loss_kernel<<<1, 512>>>(out);
}

// round 5
// speedup vs baseline: 13.3031x; 1.1841x over previous
#include <cuda_runtime.h>
#include <cuda_bf16.h>
#include <math.h>
#include <stdint.h>

#define B_ROWS 4096
#define NROWS  8192          // 2B
#define DDIM   1024
#define INV_T  10.0f
#define NTILE  64            // NROWS / 128

#define BK     32
#define BKP    40            // padded bf16 cols (80B row stride)
#define STAGES (DDIM / BK)   // 32
#define PIPE   4
#define BUFE   (128 * BKP)   // bf16 elems per operand per stage

// ---------------- device scratch ---------------------------------------------
__device__ __align__(128) __nv_bfloat16 g_reps[NROWS * DDIM];
__device__ float g_rowsum[NROWS];
__device__ float g_pos[NROWS];

// ---------------- helpers ------------------------------------------------------
__device__ __forceinline__ uint32_t smem_u32(const void* p) {
    uint32_t a;
    asm("{ .reg .u64 t; cvta.to.shared.u64 t, %1; cvt.u32.u64 %0, t; }" : "=r"(a) : "l"(p));
    return a;
}
__device__ __forceinline__ void cp16(uint32_t saddr, const void* gptr) {
    asm volatile("cp.async.cg.shared.global [%0], [%1], 16;" :: "r"(saddr), "l"(gptr) : "memory");
}
__device__ __forceinline__ void ldm_x4(uint32_t addr, uint32_t& r0, uint32_t& r1,
                                       uint32_t& r2, uint32_t& r3) {
    asm volatile("ldmatrix.sync.aligned.m8n8.x4.shared.b16 {%0,%1,%2,%3}, [%4];"
                 : "=r"(r0), "=r"(r1), "=r"(r2), "=r"(r3) : "r"(addr));
}
__device__ __forceinline__ void mma16816(float& d0, float& d1, float& d2, float& d3,
                                         uint32_t a0, uint32_t a1, uint32_t a2, uint32_t a3,
                                         uint32_t b0, uint32_t b1) {
    asm volatile(
        "mma.sync.aligned.m16n8k16.row.col.f32.bf16.bf16.f32 "
        "{%0,%1,%2,%3}, {%4,%5,%6,%7}, {%8,%9}, {%0,%1,%2,%3};"
        : "+f"(d0), "+f"(d1), "+f"(d2), "+f"(d3)
        : "r"(a0), "r"(a1), "r"(a2), "r"(a3), "r"(b0), "r"(b1));
}

// ---------------- kernel 1: row L2-normalize -> bf16, zero rowsum -------------
__global__ void normalize_kernel(const float* __restrict__ z1,
                                 const float* __restrict__ z2) {
    int row = blockIdx.x;
    const float* src = (row < B_ROWS) ? (z1 + (size_t)row * DDIM)
                                      : (z2 + (size_t)(row - B_ROWS) * DDIM);
    int t = threadIdx.x;
    float4 v = reinterpret_cast<const float4*>(src)[t];
    float s = v.x * v.x + v.y * v.y + v.z * v.z + v.w * v.w;

    __shared__ float sh[8];
    #pragma unroll
    for (int o = 16; o > 0; o >>= 1) s += __shfl_xor_sync(0xffffffffu, s, o);
    if ((t & 31) == 0) sh[t >> 5] = s;
    __syncthreads();
    if (t < 8) {
        float x = sh[t];
        #pragma unroll
        for (int o = 4; o > 0; o >>= 1) x += __shfl_xor_sync(0x000000ffu, x, o);
        if (t == 0) sh[0] = x;
    }
    __syncthreads();
    float inv = 1.0f / fmaxf(sqrtf(sh[0]), 1e-12f);

    __nv_bfloat162* dst = reinterpret_cast<__nv_bfloat162*>(g_reps + (size_t)row * DDIM);
    dst[2 * t + 0] = __floats2bfloat162_rn(v.x * inv, v.y * inv);
    dst[2 * t + 1] = __floats2bfloat162_rn(v.z * inv, v.w * inv);
    if (t == 0) g_rowsum[row] = 0.0f;
}

// ---------------- kernel 2: HMMA GEMM, 4 warps, warp tile 64x64 ---------------
extern __shared__ __nv_bfloat16 dsm[];   // [PIPE*BUFE] A, then [PIPE*BUFE] B

__global__ void __launch_bounds__(128, 2) simgemm_hmma() {
    int tid = threadIdx.x;
    int wid = tid >> 5;        // 0..3
    int lid = tid & 31;
    int wr = wid >> 1;         // 0..1 (M half)
    int wc = wid & 1;          // 0..1 (N half)

    // --- linear block id -> upper-triangle tile (I, J), J >= I ---
    int t = blockIdx.x;
    int I = (int)((129.0f - sqrtf(16641.0f - 8.0f * (float)t)) * 0.5f);
    if (I < 0) I = 0;
    if (I > NTILE - 1) I = NTILE - 1;
    while (I > 0 && I * (129 - I) / 2 > t) --I;
    while (I < NTILE - 1 && (I + 1) * (128 - I) / 2 <= t) ++I;
    int J = I + (t - I * (129 - I) / 2);
    int I0 = I * 128, J0 = J * 128;
    bool diag = (I == J);
    bool posTile = (J == I + 32);

    const __nv_bfloat16* gA = g_reps + (size_t)I0 * DDIM;
    const __nv_bfloat16* gB = g_reps + (size_t)J0 * DDIM;

    float acc[4][8][4];
    #pragma unroll
    for (int a = 0; a < 4; a++)
        #pragma unroll
        for (int b = 0; b < 8; b++)
            #pragma unroll
            for (int c = 0; c < 4; c++) acc[a][b][c] = 0.0f;

    // cp.async: 512 16B-chunks per operand per stage, 128 threads -> 4 each
    uint32_t chOff[4];
    int chRow[4], chCol[4];
    #pragma unroll
    for (int cc = 0; cc < 4; ++cc) {
        int ch = tid + cc * 128;
        chRow[cc] = ch >> 2;
        chCol[cc] = (ch & 3) << 3;
        chOff[cc] = (uint32_t)((chRow[cc] * BKP + chCol[cc]) * 2);
    }
    uint32_t aBufB[PIPE], bBufB[PIPE];
    #pragma unroll
    for (int b = 0; b < PIPE; b++) {
        aBufB[b] = smem_u32(&dsm[(size_t)b * BUFE]);
        bBufB[b] = smem_u32(&dsm[(size_t)(PIPE + b) * BUFE]);
    }

    // prologue
    #pragma unroll
    for (int s = 0; s < PIPE - 1; ++s) {
        int k0 = s * BK;
        #pragma unroll
        for (int cc = 0; cc < 4; ++cc) {
            cp16(aBufB[s] + chOff[cc], gA + (size_t)chRow[cc] * DDIM + k0 + chCol[cc]);
            cp16(bBufB[s] + chOff[cc], gB + (size_t)chRow[cc] * DDIM + k0 + chCol[cc]);
        }
        asm volatile("cp.async.commit_group;" ::: "memory");
    }

    int aRow = wr * 64 + (lid & 15);
    int aColSel = (lid >> 4) << 3;
    int bRow = wc * 64 + (lid & 7) + ((lid >> 4) << 3);
    int bColSel = ((lid >> 3) & 1) << 3;

    for (int s = 0; s < STAGES; ++s) {
        int buf = s & (PIPE - 1);
        asm volatile("cp.async.wait_group %0;" :: "n"(PIPE - 2) : "memory");
        __syncthreads();

        {
            int sn = s + PIPE - 1;
            if (sn < STAGES) {
                int nb = sn & (PIPE - 1);
                int k0 = sn * BK;
                #pragma unroll
                for (int cc = 0; cc < 4; ++cc) {
                    cp16(aBufB[nb] + chOff[cc], gA + (size_t)chRow[cc] * DDIM + k0 + chCol[cc]);
                    cp16(bBufB[nb] + chOff[cc], gB + (size_t)chRow[cc] * DDIM + k0 + chCol[cc]);
                }
            }
            asm volatile("cp.async.commit_group;" ::: "memory");
        }

        #pragma unroll
        for (int ks = 0; ks < BK / 16; ++ks) {
            int kk = ks * 16;
            uint32_t a[4][4], b[4][4];
            #pragma unroll
            for (int mt = 0; mt < 4; ++mt) {
                uint32_t addr = aBufB[buf] + (uint32_t)(((aRow + mt * 16) * BKP + kk + aColSel) * 2);
                ldm_x4(addr, a[mt][0], a[mt][1], a[mt][2], a[mt][3]);
            }
            #pragma unroll
            for (int np = 0; np < 4; ++np) {
                uint32_t addr = bBufB[buf] + (uint32_t)(((bRow + np * 16) * BKP + kk + bColSel) * 2);
                ldm_x4(addr, b[np][0], b[np][1], b[np][2], b[np][3]);
            }
            #pragma unroll
            for (int mt = 0; mt < 4; ++mt)
                #pragma unroll
                for (int nt = 0; nt < 8; ++nt) {
                    uint32_t bb0 = (nt & 1) ? b[nt >> 1][2] : b[nt >> 1][0];
                    uint32_t bb1 = (nt & 1) ? b[nt >> 1][3] : b[nt >> 1][1];
                    mma16816(acc[mt][nt][0], acc[mt][nt][1], acc[mt][nt][2], acc[mt][nt][3],
                             a[mt][0], a[mt][1], a[mt][2], a[mt][3], bb0, bb1);
                }
        }
    }

    // --- epilogue ---------------------------------------------------------------
    int rBase = I0 + wr * 64;
    int cBase = J0 + wc * 64;
    float rowacc[4][2];
    float colacc[8][2];
    #pragma unroll
    for (int x = 0; x < 4; ++x) { rowacc[x][0] = rowacc[x][1] = 0.0f; }
    #pragma unroll
    for (int x = 0; x < 8; ++x) { colacc[x][0] = colacc[x][1] = 0.0f; }

    #pragma unroll
    for (int mt = 0; mt < 4; ++mt) {
        int i0 = rBase + mt * 16 + (lid >> 2);
        int i1 = i0 + 8;
        #pragma unroll
        for (int nt = 0; nt < 8; ++nt) {
            int j0 = cBase + nt * 8 + (lid & 3) * 2;
            int j1 = j0 + 1;
            float s00 = acc[mt][nt][0] * INV_T;
            float s01 = acc[mt][nt][1] * INV_T;
            float s10 = acc[mt][nt][2] * INV_T;
            float s11 = acc[mt][nt][3] * INV_T;
            if (posTile) {
                if (j0 == i0 + B_ROWS) { g_pos[i0] = s00; g_pos[j0] = s00; }
                if (j1 == i0 + B_ROWS) { g_pos[i0] = s01; g_pos[j1] = s01; }
                if (j0 == i1 + B_ROWS) { g_pos[i1] = s10; g_pos[j0] = s10; }
                if (j1 == i1 + B_ROWS) { g_pos[i1] = s11; g_pos[j1] = s11; }
            }
            float e00 = (diag && j0 == i0) ? 0.0f : __expf(s00);
            float e01 = (diag && j1 == i0) ? 0.0f : __expf(s01);
            float e10 = (diag && j0 == i1) ? 0.0f : __expf(s10);
            float e11 = (diag && j1 == i1) ? 0.0f : __expf(s11);
            rowacc[mt][0] += e00 + e01;
            rowacc[mt][1] += e10 + e11;
            colacc[nt][0] += e00 + e10;
            colacc[nt][1] += e01 + e11;
        }
    }

    #pragma unroll
    for (int mt = 0; mt < 4; ++mt) {
        float r0 = rowacc[mt][0], r1 = rowacc[mt][1];
        #pragma unroll
        for (int o = 1; o < 4; o <<= 1) {
            r0 += __shfl_xor_sync(0xffffffffu, r0, o);
            r1 += __shfl_xor_sync(0xffffffffu, r1, o);
        }
        if ((lid & 3) == 0) {
            int i0 = rBase + mt * 16 + (lid >> 2);
            atomicAdd(&g_rowsum[i0], r0);
            atomicAdd(&g_rowsum[i0 + 8], r1);
        }
    }

    if (!diag) {
        #pragma unroll
        for (int nt = 0; nt < 8; ++nt) {
            float cA = colacc[nt][0], cB = colacc[nt][1];
            #pragma unroll
            for (int o = 4; o < 32; o <<= 1) {
                cA += __shfl_xor_sync(0xffffffffu, cA, o);
                cB += __shfl_xor_sync(0xffffffffu, cB, o);
            }
            if (lid < 4) {
                int j0 = cBase + nt * 8 + lid * 2;
                atomicAdd(&g_rowsum[j0], cA);
                atomicAdd(&g_rowsum[j0 + 1], cB);
            }
        }
    }
}

// ---------------- kernel 3: final loss -----------------------------------------
__global__ void loss_kernel(float* __restrict__ out) {
    int t = threadIdx.x;
    float s = 0.0f;
    for (int i = t; i < NROWS; i += 512) {
        float p = g_pos[i];
        s += logf(expf(p) + g_rowsum[i]) - p;
    }
    __shared__ float sh[16];
    #pragma unroll
    for (int o = 16; o > 0; o >>= 1) s += __shfl_xor_sync(0xffffffffu, s, o);
    if ((t & 31) == 0) sh[t >> 5] = s;
    __syncthreads();
    if (t < 16) {
        float x = sh[t];
        #pragma unroll
        for (int o = 8; o > 0; o >>= 1) x += __shfl_xor_sync(0x0000ffffu, x, o);
        if (t == 0) out[0] = x / (float)NROWS;
    }
}

// ---------------- launcher ------------------------------------------------------
extern "C" void kernel_launch(void* const* d_in, const int* in_sizes, int n_in,
                              void* d_out, int out_size) {
    const float* z1 = (const float*)d_in[0];
    const float* z2 = (const float*)d_in[1];
    float* out = (float*)d_out;

    const int smemBytes = 2 * PIPE * BUFE * (int)sizeof(__nv_bfloat16);   // 81920
    cudaFuncSetAttribute(simgemm_hmma, cudaFuncAttributeMaxDynamicSharedMemorySize, smemBytes);

    normalize_kernel<<<NROWS, 256>>>(z1, z2);
    simgemm_hmma<<<NTILE * (NTILE + 1) / 2, 128, smemBytes>>>();
    loss_kernel<<<1, 512>>>(out);
}